// round 7
// baseline (speedup 1.0000x reference)
#include <cuda_runtime.h>
#include <cstdint>
#include <cstddef>

#define Bn   32
#define Tn   2048
#define XD   64
#define ZD   128
#define Hh   512
#define TAUc 16
#define DD   192   // XD + ZD

// ---------------- device scratch (no allocations allowed) ----------------
__device__ float g_v[XD * TAUc * DD];                 // v[i][k][d]
__device__ float g_c[XD * TAUc];                      // c[i][k]
__device__ float g_vxT2[2 * TAUc * 32 * 64];          // [ihalf][k][d2][il*2+p]
__device__ float g_VzP[(TAUc + 1) * XD * ZD];         // prefix sums of vz over k
__device__ float g_cP[(TAUc + 1) * XD];               // prefix sums of c  over k

typedef unsigned long long u64;

__device__ __forceinline__ void fma2(u64& d, u64 a, u64 b) {
    // packed 2x fp32 FMA (sm_100+): d = a*b + d, elementwise on packed f32x2
    asm("fma.rn.f32x2 %0, %1, %2, %0;" : "+l"(d) : "l"(a), "l"(b));
}

// ---------------------------------------------------------------------------
// Kernel 1: fused W1 transpose-copy (-> influence_matrices) + v = W1@W2 + c.
// One block per (i,k) slab: reads/writes contiguous 192x512 floats, coalesced
// float4 both ways; W1 is read exactly ONCE for both outputs.
// ---------------------------------------------------------------------------
__global__ void __launch_bounds__(256) k_prep(
    const float* __restrict__ W1, const float* __restrict__ b1,
    const float* __restrict__ W2, const float* __restrict__ b2,
    float* __restrict__ IM)
{
    int blk = blockIdx.x;             // blk = i*16 + k
    int i = blk >> 4, k = blk & 15;
    const float* w1 = W1 + (size_t)blk * (DD * Hh);
    float*       im = IM + (size_t)(k * XD + i) * (DD * Hh);

    __shared__ float w2s[Hh];
    __shared__ float cred[8];
    int tid = threadIdx.x;

    for (int h = tid; h < Hh; h += 256) w2s[h] = W2[(size_t)blk * Hh + h];
    __syncthreads();

    // c[i][k] = dot(b1[i,k,:], W2[i,k,:]) + b2[i,k]
    float cp = 0.f;
    for (int h = tid; h < Hh; h += 256) cp += b1[(size_t)blk * Hh + h] * w2s[h];
    #pragma unroll
    for (int o = 16; o; o >>= 1) cp += __shfl_down_sync(0xffffffffu, cp, o);
    if ((tid & 31) == 0) cred[tid >> 5] = cp;
    __syncthreads();
    if (tid == 0) {
        float s = 0.f;
        #pragma unroll
        for (int w = 0; w < 8; w++) s += cred[w];
        g_c[blk] = s + b2[blk];
    }

    // transpose-copy + per-row dot with W2
    int warp = tid >> 5, lane = tid & 31;
    for (int d = warp; d < DD; d += 8) {
        const float4* src = (const float4*)(w1 + (size_t)d * Hh);
        float4*       dst = (float4*)(im + (size_t)d * Hh);
        const float4* w24 = (const float4*)w2s;
        float acc = 0.f;
        #pragma unroll
        for (int c4 = 0; c4 < 4; c4++) {
            float4 v4 = src[lane + c4 * 32];
            dst[lane + c4 * 32] = v4;
            float4 w4 = w24[lane + c4 * 32];
            acc += v4.x * w4.x + v4.y * w4.y + v4.z * w4.z + v4.w * w4.w;
        }
        #pragma unroll
        for (int o = 16; o; o >>= 1) acc += __shfl_down_sync(0xffffffffu, acc, o);
        if (lane == 0) g_v[(size_t)blk * DD + d] = acc;
    }
}

// ---------------------------------------------------------------------------
// Kernel 1b: prefix sums over k (for t<16 masking) + repack vx into the
// interleaved d-pair layout the conv kernel loads as LDS.64.
// ---------------------------------------------------------------------------
__global__ void __launch_bounds__(128) k_prefix()
{
    int i = blockIdx.x, t = threadIdx.x;

    if (t < ZD) {                     // vz prefix sums along k (d' = t)
        float s = 0.f;
        g_VzP[(size_t)(0 * XD + i) * ZD + t] = 0.f;
        for (int m = 1; m <= TAUc; m++) {
            s += g_v[((size_t)i * TAUc + (m - 1)) * DD + XD + t];
            g_VzP[((size_t)m * XD + i) * ZD + t] = s;
        }
    }
    if (t == 0) {                     // c prefix sums
        float cs = 0.f;
        g_cP[0 * XD + i] = 0.f;
        for (int m = 1; m <= TAUc; m++) {
            cs += g_c[i * TAUc + m - 1];
            g_cP[m * XD + i] = cs;
        }
    }
    // vx repack: g_vxT2[bz][k][d2][il*2+p] = v[i][k][2*d2+p], i = bz*32+il
    int bz = i >> 5, il = i & 31;
    for (int e = t; e < TAUc * XD; e += 128) {
        int k = e >> 6, d = e & 63;
        int d2 = d >> 1, p = d & 1;
        g_vxT2[(size_t)bz * (TAUc * 32 * 64) + (size_t)((k * 32 + d2) * 64) + il * 2 + p] =
            g_v[((size_t)i * TAUc + k) * DD + d];
    }
}

// ---------------------------------------------------------------------------
// Kernel 2: causal 16-tap, 64-channel convolution via packed f32x2 FMA.
// Block = (t-tile of 128, batch b, i-half). Thread = (i_local, t-group of 16).
// Per d-pair iter: 31 broadcast LDS.64 (x window) + 16 lane-striped LDS.64
// (vx) + 256 FFMA2 -> FMA-pipe bound at ~5.4 FMA2 per LDS.
// ---------------------------------------------------------------------------
#define CONV_SMEM (TAUc * 32 * 64 * 4 + 144 * 64 * 4)   // 131072 + 36864 B

__global__ void __launch_bounds__(256, 1) k_conv(
    const float* __restrict__ x, float* __restrict__ out)
{
    extern __shared__ float sm[];
    float* vx_sh = sm;                     // 32768 floats: [(k*32+d2)*64 + il*2 + p]
    float* x_sh  = sm + TAUc * 32 * 64;    // 9216 floats:  [r*64 + d], r=0..143

    int tt = blockIdx.x, b = blockIdx.y, bz = blockIdx.z;
    int t0 = tt * 128;
    int tid = threadIdx.x;

    const float* vsrc = g_vxT2 + (size_t)bz * (TAUc * 32 * 64);
    for (int e = tid; e < TAUc * 32 * 64; e += 256) vx_sh[e] = vsrc[e];

    const float* xb = x + (size_t)b * Tn * XD;
    for (int e = tid; e < 144 * 64; e += 256) {
        int r = e >> 6;
        int t = t0 - 16 + r;
        x_sh[e] = (t >= 0) ? xb[(size_t)t * XD + (e & 63)] : 0.f;
    }
    __syncthreads();

    int il = tid & 31, tg = tid >> 5;
    int tbase = tg * 16;                   // local t offset within the 128-tile

    u64 acc2[16];
    #pragma unroll
    for (int j = 0; j < 16; j++) acc2[j] = 0ull;

    const float* xr0 = x_sh + tbase * 64;  // row r=tbase <=> x index (t0+tbase-16)
    for (int d2 = 0; d2 < 32; d2++) {
        u64 xw[31];
        #pragma unroll
        for (int m = 0; m < 31; m++)
            xw[m] = *(const u64*)(xr0 + m * 64 + 2 * d2);   // (x[.,2d2], x[.,2d2+1])
        u64 vv[16];
        #pragma unroll
        for (int k = 0; k < 16; k++)
            vv[k] = *(const u64*)(vx_sh + (k * 32 + d2) * 64 + il * 2);
        #pragma unroll
        for (int j = 0; j < 16; j++)
            #pragma unroll
            for (int k = 0; k < 16; k++)
                fma2(acc2[j], xw[15 + j - k], vv[k]);        // x[t-1-k] * vx[i,k]
    }

    float* ob = out + ((size_t)b * Tn + t0 + tbase) * XD + bz * 32 + il;
    #pragma unroll
    for (int j = 0; j < 16; j++) {
        unsigned lo, hi;
        asm("mov.b64 {%0,%1}, %2;" : "=r"(lo), "=r"(hi) : "l"(acc2[j]));
        ob[(size_t)j * XD] = __uint_as_float(lo) + __uint_as_float(hi);  // even-d + odd-d halves
    }
}

// ---------------------------------------------------------------------------
// Kernel 3: add z-projection + bias:  out += z[b,t] . VzP[min(t,16)][i] + cP.
// Fast path (t>=16) uses the full k-sum from shared; the 16 t<16 rows per
// batch take a slow global-read path (negligible).
// ---------------------------------------------------------------------------
#define ZB_SMEM (64 * 129 * 4 + 64 * 128 * 4)   // 33024 + 32768 = 65792 B

__global__ void __launch_bounds__(256) k_zbias(
    const float* __restrict__ z, float* __restrict__ out)
{
    extern __shared__ float smz[];
    float* vzs = smz;             // [i*129 + d]  (padded: conflict-free lane stride)
    float* zs  = smz + 64 * 129;  // [tl*128 + d]

    int tt = blockIdx.x, b = blockIdx.y;
    int t0 = tt * 64;
    int tid = threadIdx.x;

    for (int e = tid; e < XD * ZD; e += 256)
        vzs[(e >> 7) * 129 + (e & 127)] = g_VzP[(size_t)TAUc * XD * ZD + e];
    const float* zb = z + ((size_t)b * Tn + t0) * ZD;
    for (int e = tid; e < 64 * ZD; e += 256) zs[e] = zb[e];
    __syncthreads();

    int i = tid & 63, tg = tid >> 6;
    float acc[16];

    if (t0 == 0 && tg == 0) {
        // t = 0..15 : m = t valid taps
        for (int j = 0; j < 16; j++) {
            int t = j;
            float a = g_cP[t * XD + i];
            for (int d = 0; d < ZD; d++)
                a += zs[j * ZD + d] * g_VzP[((size_t)t * XD + i) * ZD + d];
            acc[j] = a;
        }
    } else {
        float c16 = g_cP[TAUc * XD + i];
        #pragma unroll
        for (int j = 0; j < 16; j++) acc[j] = c16;
        for (int dc = 0; dc < ZD; dc += 32) {
            float vzr[32];
            #pragma unroll
            for (int q = 0; q < 32; q++) vzr[q] = vzs[i * 129 + dc + q];
            #pragma unroll
            for (int j = 0; j < 16; j++) {
                int tl = tg * 16 + j;
                #pragma unroll
                for (int q = 0; q < 32; q++)
                    acc[j] += zs[tl * ZD + dc + q] * vzr[q];
            }
        }
    }

    #pragma unroll
    for (int j = 0; j < 16; j++) {
        size_t t = (size_t)t0 + tg * 16 + j;
        out[((size_t)b * Tn + t) * XD + i] += acc[j];
    }
}

// ---------------------------------------------------------------------------
extern "C" void kernel_launch(void* const* d_in, const int* in_sizes, int n_in,
                              void* d_out, int out_size)
{
    const float* z  = (const float*)d_in[0];
    const float* x  = (const float*)d_in[1];
    const float* W1 = (const float*)d_in[2];
    const float* b1 = (const float*)d_in[3];
    const float* W2 = (const float*)d_in[4];
    const float* b2 = (const float*)d_in[5];

    float* out = (float*)d_out;                       // [B,T,XD] float32
    float* IM  = out + (size_t)Bn * Tn * XD;          // [TAU,XD,DD,H] float32

    cudaFuncSetAttribute(k_conv,  cudaFuncAttributeMaxDynamicSharedMemorySize, CONV_SMEM);
    cudaFuncSetAttribute(k_zbias, cudaFuncAttributeMaxDynamicSharedMemorySize, ZB_SMEM);

    k_prep<<<XD * TAUc, 256>>>(W1, b1, W2, b2, IM);
    k_prefix<<<XD, 128>>>();
    k_conv<<<dim3(Tn / 128, Bn, 2), 256, CONV_SMEM>>>(x, out);
    k_zbias<<<dim3(Tn / 64, Bn), 256, ZB_SMEM>>>(z, out);
}